// round 1
// baseline (speedup 1.0000x reference)
#include <cuda_runtime.h>
#include <cstdint>

#define B_  8
#define K_  19
#define C_  512
#define HW_ 16384

// probs scratch: 8*19*16384 floats = 9.96 MB (static __device__, allowed)
__device__ float g_probs[B_ * K_ * HW_];

// packed fp32x2 FMA (sm_100+; only reachable via PTX per SASS_QUICKREF)
#define FMA2(acc, a, b) \
    asm("fma.rn.f32x2 %0, %1, %2, %0;" : "+l"(acc) : "l"(a), "l"(b))

__device__ __forceinline__ float warpMax(float v) {
    #pragma unroll
    for (int o = 16; o; o >>= 1) v = fmaxf(v, __shfl_xor_sync(0xFFFFFFFFu, v, o));
    return v;
}
__device__ __forceinline__ float warpSum(float v) {
    #pragma unroll
    for (int o = 16; o; o >>= 1) v += __shfl_xor_sync(0xFFFFFFFFu, v, o);
    return v;
}

// ---------------------------------------------------------------------------
// Kernel 1: softmax over HW per (b,k) row. 152 CTAs x 512 threads.
// Each thread holds 32 elements in registers (8 float4), one read one write.
// ---------------------------------------------------------------------------
__global__ __launch_bounds__(512) void softmax_kernel(const float* __restrict__ aux) {
    __shared__ float sh[16];
    const int row = blockIdx.x;                       // 0..151  == b*19 + k
    const float4* x = reinterpret_cast<const float4*>(aux + (size_t)row * HW_);
    float4*       p = reinterpret_cast<float4*>(g_probs + (size_t)row * HW_);
    const int tid  = threadIdx.x;
    const int lane = tid & 31, w = tid >> 5;

    float4 v[8];
    float m = -3.402823466e38f;
    #pragma unroll
    for (int i = 0; i < 8; i++) {
        v[i] = x[tid + i * 512];
        m = fmaxf(m, fmaxf(fmaxf(v[i].x, v[i].y), fmaxf(v[i].z, v[i].w)));
    }
    m = warpMax(m);
    if (lane == 0) sh[w] = m;
    __syncthreads();
    if (w == 0) {
        float t = (lane < 16) ? sh[lane] : -3.402823466e38f;
        t = warpMax(t);
        if (lane == 0) sh[0] = t;
    }
    __syncthreads();
    m = sh[0];
    __syncthreads();                                   // before reusing sh

    float s = 0.0f;
    #pragma unroll
    for (int i = 0; i < 8; i++) {
        v[i].x = __expf(v[i].x - m);
        v[i].y = __expf(v[i].y - m);
        v[i].z = __expf(v[i].z - m);
        v[i].w = __expf(v[i].w - m);
        s += (v[i].x + v[i].y) + (v[i].z + v[i].w);
    }
    s = warpSum(s);
    if (lane == 0) sh[w] = s;
    __syncthreads();
    if (w == 0) {
        float t = (lane < 16) ? sh[lane] : 0.0f;
        t = warpSum(t);
        if (lane == 0) sh[0] = t;
    }
    __syncthreads();
    const float inv = 1.0f / sh[0];

    #pragma unroll
    for (int i = 0; i < 8; i++) {
        v[i].x *= inv; v[i].y *= inv; v[i].z *= inv; v[i].w *= inv;
        p[tid + i * 512] = v[i];
    }
}

// ---------------------------------------------------------------------------
// Kernel 2: ctx[b,c,k] = sum_s probs[b,k,s] * feats[b,c,s]
//
// grid = 8 b * 32 c-groups = 256 CTAs, 256 threads (8 warps).
//   CTA: (b, c0..c0+15).  Warp w: s-range [w*2048, (w+1)*2048).
//   Lane layout: c_sub = lane>>2 (0..7), s_sub = lane&3.
//   Each lane owns c = c0+c_sub and c0+c_sub+8, and 4 consecutive s per step.
//   -> probs LDG.128 is 4-way address-deduplicated across the warp (64B/instr)
//      and each probs value feeds 16 c.  All math in packed f32x2.
// Accumulators: 19k x 2c f32x2 = 76 regs. Cross-warp reduce via smem.
// ---------------------------------------------------------------------------
__global__ __launch_bounds__(256, 2) void gather_kernel(const float* __restrict__ feats,
                                                        float* __restrict__ out) {
    __shared__ float red[8][16][K_];                  // 9728 B

    const int b  = blockIdx.x >> 5;
    const int c0 = (blockIdx.x & 31) * 16;
    const int tid = threadIdx.x;
    const int w = tid >> 5, lane = tid & 31;
    const int c_sub = lane >> 2, s_sub = lane & 3;

    const float* fbase = feats  + ((size_t)(b * C_) + c0 + c_sub) * HW_;
    const float* pbase = g_probs + (size_t)(b * K_) * HW_;

    unsigned long long acc[K_][2];
    #pragma unroll
    for (int k = 0; k < K_; k++) { acc[k][0] = 0ull; acc[k][1] = 0ull; }

    const int s0 = w * 2048 + s_sub * 4;

    #pragma unroll 2
    for (int it = 0; it < 128; ++it) {
        const int s = s0 + it * 16;
        const ulonglong2 f0 = *reinterpret_cast<const ulonglong2*>(fbase + s);
        const ulonglong2 f1 = *reinterpret_cast<const ulonglong2*>(fbase + 8 * HW_ + s);
        #pragma unroll
        for (int k = 0; k < K_; k++) {
            const ulonglong2 p =
                *reinterpret_cast<const ulonglong2*>(pbase + (size_t)k * HW_ + s);
            FMA2(acc[k][0], p.x, f0.x);
            FMA2(acc[k][0], p.y, f0.y);
            FMA2(acc[k][1], p.x, f1.x);
            FMA2(acc[k][1], p.y, f1.y);
        }
    }

    // lane-local + quad reduce, then stage per-warp partials
    #pragma unroll
    for (int k = 0; k < K_; k++) {
        #pragma unroll
        for (int cp = 0; cp < 2; cp++) {
            float2 v;
            asm("mov.b64 {%0, %1}, %2;" : "=f"(v.x), "=f"(v.y) : "l"(acc[k][cp]));
            float sum = v.x + v.y;
            sum += __shfl_xor_sync(0xFFFFFFFFu, sum, 1);
            sum += __shfl_xor_sync(0xFFFFFFFFu, sum, 2);
            if (s_sub == 0) red[w][c_sub + 8 * cp][k] = sum;
        }
    }
    __syncthreads();

    // cross-warp reduce + store: 16*19 = 304 outputs per CTA, each written once
    for (int idx = tid; idx < 16 * K_; idx += 256) {
        const int cl = idx / K_, k = idx % K_;
        float s = 0.0f;
        #pragma unroll
        for (int ww = 0; ww < 8; ++ww) s += red[ww][cl][k];
        out[((size_t)b * C_ + c0 + cl) * K_ + k] = s;
    }
}

extern "C" void kernel_launch(void* const* d_in, const int* in_sizes, int n_in,
                              void* d_out, int out_size) {
    const float* feats = (const float*)d_in[0];   // bb_feats [8,512,128,128]
    const float* aux   = (const float*)d_in[1];   // aux_out  [8,19,128,128]
    float* out = (float*)d_out;                   // [8,512,19,1] f32

    softmax_kernel<<<B_ * K_, 512>>>(aux);
    gather_kernel<<<B_ * 32, 256>>>(feats, out);
}